// round 2
// baseline (speedup 1.0000x reference)
#include <cuda_runtime.h>
#include <cstdint>

// Problem constants (fixed by the reference)
#define NUM_CLASSES 32000
#define C4          (NUM_CLASSES / 4)   // 8000 float4 per row
#define ALPHA       0.95f
#define THREADS     512

__global__ __launch_bounds__(THREADS)
void smooth_kernel(const float* __restrict__ logits,
                   const int* __restrict__ labels,   // int32: JAX w/o x64 downcasts int64
                   float* __restrict__ out)
{
    const int row = blockIdx.x;
    const size_t row_off = (size_t)row * NUM_CLASSES;
    const float4* __restrict__ in4  = reinterpret_cast<const float4*>(logits + row_off);
    float4* __restrict__       out4 = reinterpret_cast<float4*>(out + row_off);

    const int label = labels[row];

    // ---- Pass 1: row sum (fills L2 with this row) ----
    float local = 0.0f;
    for (int i = threadIdx.x; i < C4; i += THREADS) {
        float4 v = in4[i];
        local += (v.x + v.y) + (v.z + v.w);
    }

    // warp reduce
    #pragma unroll
    for (int o = 16; o > 0; o >>= 1)
        local += __shfl_down_sync(0xffffffffu, local, o);

    __shared__ float sdata[THREADS / 32];
    const int wid = threadIdx.x >> 5;
    const int lid = threadIdx.x & 31;
    if (lid == 0) sdata[wid] = local;
    __syncthreads();

    if (wid == 0) {
        float v = (lid < (THREADS / 32)) ? sdata[lid] : 0.0f;
        #pragma unroll
        for (int o = 16; o > 0; o >>= 1)
            v += __shfl_down_sync(0xffffffffu, v, o);
        if (lid == 0) sdata[0] = v;
    }
    __syncthreads();

    const float S = sdata[0];
    const float t = __ldg(logits + row_off + label);
    const float s = ALPHA / (1.0f + S - 2.0f * t);
    const float corr = 1.0f - s * S;   // added at the label position

    const int lvec  = label >> 2;
    const int lcomp = label & 3;

    // ---- Pass 2: scale + write (reads hit L2; stores evict-first) ----
    for (int i = threadIdx.x; i < C4; i += THREADS) {
        float4 v = in4[i];
        float4 o;
        o.x = s * v.x;
        o.y = s * v.y;
        o.z = s * v.z;
        o.w = s * v.w;
        if (i == lvec) {
            reinterpret_cast<float*>(&o)[lcomp] += corr;
        }
        __stcs(&out4[i], o);
    }
}

extern "C" void kernel_launch(void* const* d_in, const int* in_sizes, int n_in,
                              void* d_out, int out_size)
{
    const float* logits = (const float*)d_in[0];
    const int*   labels = (const int*)d_in[1];
    float*       out    = (float*)d_out;

    const int batch = in_sizes[1];   // labels has BATCH elements

    smooth_kernel<<<batch, THREADS>>>(logits, labels, out);
}

// round 3
// speedup vs baseline: 1.2109x; 1.2109x over previous
#include <cuda_runtime.h>
#include <cstdint>

#define NUM_CLASSES 32000
#define C4          8000          // float4 per row
#define ALPHA       0.95f
#define THREADS     512
#define KCHUNKS     16            // ceil(8000 / 512)

__global__ __launch_bounds__(THREADS, 1)
void smooth_kernel(const float* __restrict__ logits,
                   const int* __restrict__ labels,
                   float* __restrict__ out,
                   int batch)
{
    __shared__ float swarp[THREADS / 32];
    __shared__ float sS;
    __shared__ float sT;

    const int tid = threadIdx.x;
    const int wid = tid >> 5;
    const int lid = tid & 31;

    for (int row = blockIdx.x; row < batch; row += gridDim.x) {
        const size_t off = (size_t)row * NUM_CLASSES;
        const float4* __restrict__ in4  = reinterpret_cast<const float4*>(logits + off);
        float4* __restrict__       out4 = reinterpret_cast<float4*>(out + off);

        const int label = __ldg(labels + row);
        const int lvec  = label >> 2;
        const int lcomp = label & 3;

        // ---- Pass 1: stream row into registers, accumulate sum ----
        float4 d[KCHUNKS];
        float  local = 0.0f;
        #pragma unroll
        for (int k = 0; k < KCHUNKS; k++) {
            const int i = tid + k * THREADS;
            float4 v = make_float4(0.f, 0.f, 0.f, 0.f);
            if (i < C4) v = __ldcs(in4 + i);
            d[k] = v;
            local += (v.x + v.y) + (v.z + v.w);
            if (i == lvec) {   // exactly one thread per row owns the label element
                sT = (lcomp == 0) ? v.x : (lcomp == 1) ? v.y : (lcomp == 2) ? v.z : v.w;
            }
        }

        // ---- Block reduce S ----
        #pragma unroll
        for (int o = 16; o > 0; o >>= 1)
            local += __shfl_down_sync(0xffffffffu, local, o);
        if (lid == 0) swarp[wid] = local;
        __syncthreads();
        if (wid == 0) {
            float v = (lid < (THREADS / 32)) ? swarp[lid] : 0.0f;
            #pragma unroll
            for (int o = 8; o > 0; o >>= 1)
                v += __shfl_down_sync(0xffffffffu, v, o);
            if (lid == 0) sS = v;
        }
        __syncthreads();

        const float S    = sS;
        const float t    = sT;
        const float s    = ALPHA / (1.0f + S - 2.0f * t);
        const float corr = 1.0f - s * S;

        // ---- Pass 2: scale registers, patch label, stream out ----
        #pragma unroll
        for (int k = 0; k < KCHUNKS; k++) {
            const int i = tid + k * THREADS;
            if (i < C4) {
                const float4 v = d[k];
                float4 o4 = make_float4(s * v.x, s * v.y, s * v.z, s * v.w);
                if (i == lvec) {
                    o4.x += (lcomp == 0) ? corr : 0.0f;
                    o4.y += (lcomp == 1) ? corr : 0.0f;
                    o4.z += (lcomp == 2) ? corr : 0.0f;
                    o4.w += (lcomp == 3) ? corr : 0.0f;
                }
                __stcs(out4 + i, o4);
            }
        }
        __syncthreads();   // protect sS/sT/swarp before next row reuses them
    }
}

extern "C" void kernel_launch(void* const* d_in, const int* in_sizes, int n_in,
                              void* d_out, int out_size)
{
    const float* logits = (const float*)d_in[0];
    const int*   labels = (const int*)d_in[1];
    float*       out    = (float*)d_out;

    const int batch = in_sizes[1];

    // Host-side query: executes once during graph capture, zero cost at replay.
    int dev = 0, sms = 148;
    cudaGetDevice(&dev);
    cudaDeviceGetAttribute(&sms, cudaDevAttrMultiProcessorCount, dev);
    int grid = sms < batch ? sms : batch;

    smooth_kernel<<<grid, THREADS>>>(logits, labels, out, batch);
}

// round 4
// speedup vs baseline: 1.2394x; 1.0235x over previous
#include <cuda_runtime.h>
#include <cstdint>

#define NUM_CLASSES   32000
#define ROW_BYTES     128000               // 32000 * 4
#define ALPHA         0.95f

#define THREADS       512
#define NCONS         480                  // 15 consumer warps
#define PROD_WARP     15

#define CHUNKS_PER_ROW 8
#define CHUNK_BYTES   16000                // 4000 floats, mult of 16
#define CHUNK_F4      1000                 // float4 per chunk
#define NSLOTS        12                   // 12 * 16000 = 192000 B ring

// smem layout (dynamic):
//   [0,96)     full mbarriers  (12 x 8B)
//   [96,192)   empty mbarriers (12 x 8B)
//   [192,256)  swarp[15]
//   [256,264)  sS
//   [512, 512+192000)  ring slots
#define OFF_FULL   0
#define OFF_EMPTY  96
#define OFF_SWARP  192
#define OFF_SS     256
#define OFF_SLOTS  512
#define SMEM_TOTAL (OFF_SLOTS + NSLOTS * CHUNK_BYTES)   // 192512

__device__ __forceinline__ uint32_t smem_u32(const void* p) {
    uint32_t a;
    asm("{ .reg .u64 t; cvta.to.shared.u64 t, %1; cvt.u32.u64 %0, t; }"
        : "=r"(a) : "l"(p));
    return a;
}
__device__ __forceinline__ void mbar_init(uint32_t addr, uint32_t cnt) {
    asm volatile("mbarrier.init.shared.b64 [%0], %1;" :: "r"(addr), "r"(cnt) : "memory");
}
__device__ __forceinline__ void mbar_expect_tx(uint32_t addr, uint32_t bytes) {
    asm volatile("mbarrier.arrive.expect_tx.shared.b64 _, [%0], %1;"
                 :: "r"(addr), "r"(bytes) : "memory");
}
__device__ __forceinline__ void mbar_arrive(uint32_t addr) {
    asm volatile("mbarrier.arrive.shared.b64 _, [%0];" :: "r"(addr) : "memory");
}
__device__ __forceinline__ void mbar_wait(uint32_t addr, uint32_t parity) {
    uint32_t done;
    asm volatile(
        "{\n\t.reg .pred p;\n\t"
        "mbarrier.try_wait.parity.acquire.cta.shared::cta.b64 p, [%1], %2;\n\t"
        "selp.b32 %0, 1, 0, p;\n\t}"
        : "=r"(done) : "r"(addr), "r"(parity) : "memory");
    if (!done) {
        asm volatile(
            "{\n\t.reg .pred P1;\n\t"
            "W_%=:\n\t"
            "mbarrier.try_wait.parity.acquire.cta.shared::cta.b64 P1, [%0], %1, 0x989680;\n\t"
            "@P1 bra.uni D_%=;\n\t"
            "bra.uni W_%=;\n\t"
            "D_%=:\n\t}"
            :: "r"(addr), "r"(parity) : "memory");
    }
}
__device__ __forceinline__ void bulk_g2s(uint32_t dst, const void* src,
                                         uint32_t bytes, uint32_t mbar) {
    asm volatile(
        "cp.async.bulk.shared::cluster.global.mbarrier::complete_tx::bytes "
        "[%0], [%1], %2, [%3];"
        :: "r"(dst), "l"(src), "r"(bytes), "r"(mbar) : "memory");
}

extern __shared__ char smem[];

__global__ __launch_bounds__(THREADS, 1)
void smooth_kernel(const float* __restrict__ in,
                   const int* __restrict__ labels,
                   float* __restrict__ out,
                   int batch)
{
    const uint32_t sbase  = smem_u32(smem);
    const uint32_t full0  = sbase + OFF_FULL;
    const uint32_t empty0 = sbase + OFF_EMPTY;
    float* swarp = reinterpret_cast<float*>(smem + OFF_SWARP);
    float* sSp   = reinterpret_cast<float*>(smem + OFF_SS);
    char*  slots = smem + OFF_SLOTS;
    const uint32_t slots_u = sbase + OFF_SLOTS;

    const int tid = threadIdx.x;
    const int wid = tid >> 5;
    const int lid = tid & 31;

    if (tid == 0) {
        #pragma unroll
        for (int s = 0; s < NSLOTS; s++) {
            mbar_init(full0  + 8u * s, 1);        // expect_tx arrive
            mbar_init(empty0 + 8u * s, 15);       // one per consumer warp
        }
    }
    __syncthreads();

    if (wid == PROD_WARP) {
        // ---------------- producer ----------------
        if (lid == 0) {
            int slot = 0, pphase = 1;             // flipped: first empty-wait passes
            for (int r = blockIdx.x; r < batch; r += gridDim.x) {
                const char* src = reinterpret_cast<const char*>(in)
                                + (size_t)r * ROW_BYTES;
                #pragma unroll
                for (int c = 0; c < CHUNKS_PER_ROW; c++) {
                    mbar_wait(empty0 + 8u * slot, (uint32_t)pphase);
                    mbar_expect_tx(full0 + 8u * slot, CHUNK_BYTES);
                    bulk_g2s(slots_u + (uint32_t)slot * CHUNK_BYTES,
                             src + (size_t)c * CHUNK_BYTES,
                             CHUNK_BYTES,
                             full0 + 8u * slot);
                    if (++slot == NSLOTS) { slot = 0; pphase ^= 1; }
                }
            }
        }
    } else {
        // ---------------- consumers (480 threads) ----------------
        int slot = 0, cphase = 0;
        for (int r = blockIdx.x; r < batch; r += gridDim.x) {
            const int label = __ldg(labels + r);
            const int lvec  = label >> 2;
            const int lcomp = label & 3;
            const int c_l   = lvec / CHUNK_F4;    // chunk holding label elem
            const int loff  = lvec % CHUNK_F4;

            const int row_slot0 = slot;

            // -- sum phase: consume chunks as they land (keep them resident) --
            float local = 0.0f;
            for (int c = 0; c < CHUNKS_PER_ROW; c++) {
                mbar_wait(full0 + 8u * slot, (uint32_t)cphase);
                const float4* ch =
                    reinterpret_cast<const float4*>(slots + (size_t)slot * CHUNK_BYTES);
                for (int i = tid; i < CHUNK_F4; i += NCONS) {
                    float4 v = ch[i];
                    local += (v.x + v.y) + (v.z + v.w);
                }
                if (++slot == NSLOTS) { slot = 0; cphase ^= 1; }
            }

            // -- reduce across 15 warps --
            #pragma unroll
            for (int o = 16; o > 0; o >>= 1)
                local += __shfl_down_sync(0xffffffffu, local, o);
            if (lid == 0) swarp[wid] = local;
            asm volatile("bar.sync 1, %0;" :: "n"(NCONS) : "memory");
            if (wid == 0) {
                float v = (lid < 15) ? swarp[lid] : 0.0f;
                #pragma unroll
                for (int o = 8; o > 0; o >>= 1)
                    v += __shfl_down_sync(0xffffffffu, v, o);
                if (lid == 0) *sSp = v;
            }
            asm volatile("bar.sync 1, %0;" :: "n"(NCONS) : "memory");

            const float S = *sSp;
            int lslot = row_slot0 + c_l; if (lslot >= NSLOTS) lslot -= NSLOTS;
            const float t = *reinterpret_cast<const float*>(
                slots + (size_t)lslot * CHUNK_BYTES + ((size_t)loff * 16 + (size_t)lcomp * 4));
            const float s    = ALPHA / (1.0f + S - 2.0f * t);
            const float corr = 1.0f - s * S;

            // -- scale phase: re-read smem, patch label, stream out, free slots --
            float* orow = out + (size_t)r * NUM_CLASSES;
            int sslot = row_slot0;
            for (int c = 0; c < CHUNKS_PER_ROW; c++) {
                const float4* ch =
                    reinterpret_cast<const float4*>(slots + (size_t)sslot * CHUNK_BYTES);
                float4* och = reinterpret_cast<float4*>(orow) + c * CHUNK_F4;
                const bool lchunk = (c == c_l);
                for (int i = tid; i < CHUNK_F4; i += NCONS) {
                    float4 v = ch[i];
                    float4 o = make_float4(s * v.x, s * v.y, s * v.z, s * v.w);
                    if (lchunk && i == loff) {
                        o.x += (lcomp == 0) ? corr : 0.0f;
                        o.y += (lcomp == 1) ? corr : 0.0f;
                        o.z += (lcomp == 2) ? corr : 0.0f;
                        o.w += (lcomp == 3) ? corr : 0.0f;
                    }
                    __stcs(och + i, o);
                }
                __syncwarp();
                if (lid == 0) mbar_arrive(empty0 + 8u * sslot);
                if (++sslot == NSLOTS) sslot = 0;
            }
        }
    }
}

extern "C" void kernel_launch(void* const* d_in, const int* in_sizes, int n_in,
                              void* d_out, int out_size)
{
    const float* logits = (const float*)d_in[0];
    const int*   labels = (const int*)d_in[1];
    float*       out    = (float*)d_out;

    const int batch = in_sizes[1];

    cudaFuncSetAttribute(smooth_kernel,
                         cudaFuncAttributeMaxDynamicSharedMemorySize, SMEM_TOTAL);

    int dev = 0, sms = 148;
    cudaGetDevice(&dev);
    cudaDeviceGetAttribute(&sms, cudaDevAttrMultiProcessorCount, dev);
    int grid = sms < batch ? sms : batch;

    smooth_kernel<<<grid, THREADS, SMEM_TOTAL>>>(logits, labels, out, batch);
}

// round 5
// speedup vs baseline: 1.2858x; 1.0374x over previous
#include <cuda_runtime.h>
#include <cstdint>

#define NUM_CLASSES    32000
#define ROW_BYTES      128000
#define ALPHA          0.95f

#define THREADS        512
#define NCONS          480            // 15 consumer warps
#define PROD_WARP      15

#define CHUNKS_PER_ROW 8
#define CHUNK_BYTES    16000
#define CHUNK_F4       1000
#define CHUNK_FLOATS   4000
#define NSLOTS         14             // 14 * 16000 = 224000 B ring

// smem layout (dynamic):
//   [0,112)    full mbarriers   (14 x 8B)
//   [128,240)  scaled mbarriers (14 x 8B)
//   [256,316)  swarp[15]
//   [320,324)  sS
//   [512, 512+224000) ring slots
#define OFF_FULL    0
#define OFF_SCALED  128
#define OFF_SWARP   256
#define OFF_SS      320
#define OFF_SLOTS   512
#define SMEM_TOTAL  (OFF_SLOTS + NSLOTS * CHUNK_BYTES)   // 224512

__device__ __forceinline__ uint32_t smem_u32(const void* p) {
    uint32_t a;
    asm("{ .reg .u64 t; cvta.to.shared.u64 t, %1; cvt.u32.u64 %0, t; }"
        : "=r"(a) : "l"(p));
    return a;
}
__device__ __forceinline__ void mbar_init(uint32_t addr, uint32_t cnt) {
    asm volatile("mbarrier.init.shared.b64 [%0], %1;" :: "r"(addr), "r"(cnt) : "memory");
}
__device__ __forceinline__ void mbar_expect_tx(uint32_t addr, uint32_t bytes) {
    asm volatile("mbarrier.arrive.expect_tx.shared.b64 _, [%0], %1;"
                 :: "r"(addr), "r"(bytes) : "memory");
}
__device__ __forceinline__ void mbar_arrive(uint32_t addr) {
    asm volatile("mbarrier.arrive.shared.b64 _, [%0];" :: "r"(addr) : "memory");
}
__device__ __forceinline__ void mbar_wait(uint32_t addr, uint32_t parity) {
    uint32_t done;
    asm volatile(
        "{\n\t.reg .pred p;\n\t"
        "mbarrier.try_wait.parity.acquire.cta.shared::cta.b64 p, [%1], %2;\n\t"
        "selp.b32 %0, 1, 0, p;\n\t}"
        : "=r"(done) : "r"(addr), "r"(parity) : "memory");
    if (!done) {
        asm volatile(
            "{\n\t.reg .pred P1;\n\t"
            "W_%=:\n\t"
            "mbarrier.try_wait.parity.acquire.cta.shared::cta.b64 P1, [%0], %1, 0x989680;\n\t"
            "@P1 bra.uni D_%=;\n\t"
            "bra.uni W_%=;\n\t"
            "D_%=:\n\t}"
            :: "r"(addr), "r"(parity) : "memory");
    }
}
__device__ __forceinline__ void bulk_g2s(uint32_t dst, const void* src,
                                         uint32_t bytes, uint32_t mbar) {
    asm volatile(
        "cp.async.bulk.shared::cluster.global.mbarrier::complete_tx::bytes "
        "[%0], [%1], %2, [%3];"
        :: "r"(dst), "l"(src), "r"(bytes), "r"(mbar) : "memory");
}
__device__ __forceinline__ void bulk_s2g(void* dst, uint32_t src, uint32_t bytes) {
    asm volatile(
        "cp.async.bulk.global.shared::cta.bulk_group [%0], [%1], %2;"
        :: "l"(dst), "r"(src), "r"(bytes) : "memory");
}
__device__ __forceinline__ void bulk_commit() {
    asm volatile("cp.async.bulk.commit_group;" ::: "memory");
}
__device__ __forceinline__ void bulk_wait_read0() {
    asm volatile("cp.async.bulk.wait_group.read 0;" ::: "memory");
}
__device__ __forceinline__ void bulk_wait_all() {
    asm volatile("cp.async.bulk.wait_group 0;" ::: "memory");
}
__device__ __forceinline__ void fence_async_shared() {
    asm volatile("fence.proxy.async.shared::cta;" ::: "memory");
}

extern __shared__ char smem[];

__global__ __launch_bounds__(THREADS, 1)
void smooth_kernel(const float* __restrict__ in,
                   const int* __restrict__ labels,
                   float* __restrict__ out,
                   int batch)
{
    const uint32_t sbase   = smem_u32(smem);
    const uint32_t full0   = sbase + OFF_FULL;
    const uint32_t scaled0 = sbase + OFF_SCALED;
    float* swarp = reinterpret_cast<float*>(smem + OFF_SWARP);
    float* sSp   = reinterpret_cast<float*>(smem + OFF_SS);
    char*  slots = smem + OFF_SLOTS;
    const uint32_t slots_u = sbase + OFF_SLOTS;

    const int tid = threadIdx.x;
    const int wid = tid >> 5;
    const int lid = tid & 31;

    if (tid == 0) {
        #pragma unroll
        for (int s = 0; s < NSLOTS; s++) {
            mbar_init(full0   + 8u * s, 1);    // expect_tx completion
            mbar_init(scaled0 + 8u * s, 15);   // one arrive per consumer warp
        }
    }
    __syncthreads();

    if (wid == PROD_WARP) {
        // ---------- producer: TMA loads in, TMA stores out ----------
        if (lid == 0) {
            int slot = 0, sphase = 1;          // flipped: first waits pass
            unsigned g = 0;                    // global chunk counter
            float* dsts[NSLOTS];               // output addr of slot occupant

            for (int r = blockIdx.x; r < batch; r += gridDim.x) {
                const char* src = reinterpret_cast<const char*>(in)
                                + (size_t)r * ROW_BYTES;
                float* odst = out + (size_t)r * NUM_CLASSES;
                #pragma unroll
                for (int c = 0; c < CHUNKS_PER_ROW; c++) {
                    // wait until previous occupant of this slot is fully scaled
                    mbar_wait(scaled0 + 8u * slot, (uint32_t)sphase);
                    if (g >= NSLOTS) {
                        // flush old occupant to global, then ensure its smem
                        // read is done before the load below overwrites it
                        fence_async_shared();
                        bulk_s2g(dsts[slot],
                                 slots_u + (uint32_t)slot * CHUNK_BYTES,
                                 CHUNK_BYTES);
                        bulk_commit();
                        bulk_wait_read0();
                    }
                    dsts[slot] = odst + (size_t)c * CHUNK_FLOATS;
                    mbar_expect_tx(full0 + 8u * slot, CHUNK_BYTES);
                    bulk_g2s(slots_u + (uint32_t)slot * CHUNK_BYTES,
                             src + (size_t)c * CHUNK_BYTES,
                             CHUNK_BYTES,
                             full0 + 8u * slot);
                    g++;
                    if (++slot == NSLOTS) { slot = 0; sphase ^= 1; }
                }
            }
            // drain: store the last NSLOTS occupants
            #pragma unroll
            for (int k = 0; k < NSLOTS; k++) {
                mbar_wait(scaled0 + 8u * slot, (uint32_t)sphase);
                if (g >= NSLOTS) {
                    fence_async_shared();
                    bulk_s2g(dsts[slot],
                             slots_u + (uint32_t)slot * CHUNK_BYTES,
                             CHUNK_BYTES);
                    bulk_commit();
                }
                g++;
                if (++slot == NSLOTS) { slot = 0; sphase ^= 1; }
            }
            bulk_wait_all();   // all writes committed before kernel exit
        }
    } else {
        // ---------- consumers: sum, reduce, scale in place ----------
        int slot = 0, cphase = 0;
        for (int r = blockIdx.x; r < batch; r += gridDim.x) {
            const int label = __ldg(labels + r);
            const int lvec  = label >> 2;
            const int lcomp = label & 3;
            const int c_l   = lvec / CHUNK_F4;
            const int loff  = lvec % CHUNK_F4;

            const int row_slot0 = slot;

            // -- sum phase --
            float local = 0.0f;
            for (int c = 0; c < CHUNKS_PER_ROW; c++) {
                mbar_wait(full0 + 8u * slot, (uint32_t)cphase);
                const float4* ch =
                    reinterpret_cast<const float4*>(slots + (size_t)slot * CHUNK_BYTES);
                for (int i = tid; i < CHUNK_F4; i += NCONS) {
                    float4 v = ch[i];
                    local += (v.x + v.y) + (v.z + v.w);
                }
                if (++slot == NSLOTS) { slot = 0; cphase ^= 1; }
            }

            // read label element now: all chunks resident, nothing overwritten yet
            int lslot = row_slot0 + c_l; if (lslot >= NSLOTS) lslot -= NSLOTS;
            const float t = *reinterpret_cast<const float*>(
                slots + (size_t)lslot * CHUNK_BYTES
                      + ((size_t)loff * 16 + (size_t)lcomp * 4));

            // -- reduce S across 15 warps --
            #pragma unroll
            for (int o = 16; o > 0; o >>= 1)
                local += __shfl_down_sync(0xffffffffu, local, o);
            if (lid == 0) swarp[wid] = local;
            asm volatile("bar.sync 1, %0;" :: "n"(NCONS) : "memory");
            if (wid == 0) {
                float v = (lid < 15) ? swarp[lid] : 0.0f;
                #pragma unroll
                for (int o = 8; o > 0; o >>= 1)
                    v += __shfl_down_sync(0xffffffffu, v, o);
                if (lid == 0) *sSp = v;
            }
            asm volatile("bar.sync 1, %0;" :: "n"(NCONS) : "memory");

            const float S    = *sSp;
            const float s    = ALPHA / (1.0f + S - 2.0f * t);
            const float corr = 1.0f - s * S;

            // -- scale phase: in-place smem, then hand slot to producer --
            int sslot = row_slot0;
            for (int c = 0; c < CHUNKS_PER_ROW; c++) {
                float4* ch =
                    reinterpret_cast<float4*>(slots + (size_t)sslot * CHUNK_BYTES);
                const bool lchunk = (c == c_l);
                for (int i = tid; i < CHUNK_F4; i += NCONS) {
                    float4 v = ch[i];
                    float4 o = make_float4(s * v.x, s * v.y, s * v.z, s * v.w);
                    if (lchunk && i == loff) {
                        o.x += (lcomp == 0) ? corr : 0.0f;
                        o.y += (lcomp == 1) ? corr : 0.0f;
                        o.z += (lcomp == 2) ? corr : 0.0f;
                        o.w += (lcomp == 3) ? corr : 0.0f;
                    }
                    ch[i] = o;
                }
                __syncwarp();
                if (lid == 0) mbar_arrive(scaled0 + 8u * sslot);
                if (++sslot == NSLOTS) sslot = 0;
            }
        }
    }
}

extern "C" void kernel_launch(void* const* d_in, const int* in_sizes, int n_in,
                              void* d_out, int out_size)
{
    const float* logits = (const float*)d_in[0];
    const int*   labels = (const int*)d_in[1];
    float*       out    = (float*)d_out;

    const int batch = in_sizes[1];

    cudaFuncSetAttribute(smooth_kernel,
                         cudaFuncAttributeMaxDynamicSharedMemorySize, SMEM_TOTAL);

    int dev = 0, sms = 148;
    cudaGetDevice(&dev);
    cudaDeviceGetAttribute(&sms, cudaDevAttrMultiProcessorCount, dev);
    int grid = sms < batch ? sms : batch;

    smooth_kernel<<<grid, THREADS, SMEM_TOTAL>>>(logits, labels, out, batch);
}